// round 7
// baseline (speedup 1.0000x reference)
#include <cuda_runtime.h>
#include <math.h>

// ---------------- problem constants ----------------
constexpr int Bb  = 2;
constexpr int Ss  = 1024;
constexpr int Dd  = 2048;
constexpr int Hh  = 16;
constexpr int DHh = 128;
constexpr int HD  = Hh * DHh;     // 2048
constexpr int Ee  = 8;
constexpr int KK  = 2;
constexpr int Ii  = 1408;
constexpr int ISs = 5632;
constexpr int Tt  = Bb * Ss;      // 2048 tokens
constexpr float EPSf   = 1e-6f;
constexpr float SCALEf = 0.08838834764831845f;   // 1/sqrt(128)

// ---------------- scratch layout (single __device__ arena) ----------------
constexpr long TD   = (long)Tt * Dd;                 // 4,194,304
constexpr long SCSZ = (long)Bb * Hh * Ss * Ss;       // 33,554,432
constexpr long GSZ  = (long)Tt * KK * Ii;            // 5,767,168
constexpr long MSZ  = (long)Tt * KK * Dd;            // 8,388,608
constexpr long SGSZ = (long)Tt * ISs;                // 11,534,336

constexpr long O_H1   = 0;
constexpr long O_Q    = O_H1  + TD;
constexpr long O_K    = O_Q   + TD;
constexpr long O_V    = O_K   + TD;
constexpr long O_SC   = O_V   + TD;
constexpr long O_ATT  = O_SC  + SCSZ;
constexpr long O_RES  = O_ATT + TD;
constexpr long O_H2   = O_RES + TD;
constexpr long O_G    = O_H2  + TD;
constexpr long O_U    = O_G   + GSZ;
constexpr long O_MOE  = O_U   + GSZ;
constexpr long O_SG   = O_MOE + MSZ;
constexpr long O_SU   = O_SG  + SGSZ;
constexpr long O_SH   = O_SU  + SGSZ;
constexpr long O_TOPV = O_SH  + TD;
constexpr long O_SGATE= O_TOPV+ (long)Tt * KK;
constexpr long GBUF_TOTAL = O_SGATE + Tt;

__device__ float g_buf[GBUF_TOTAL];
__device__ int   g_cnt[Ee];
__device__ int   g_tokA[Ee * Tt];
__device__ int   g_dstC[Ee * Tt];

// ---------------- generic fp32 tiled GEMM (128x128, KTILE=16, float4 loads) ----
// C[M,N] = A[M,K] * B   (B row-major KxN, or TRANS_B: B row-major NxK -> A*B^T)
// optional: bias add, device-side M (mPtr), A row gather (idxA), C row scatter
// (idxC), batching via blockIdx.z with (outer, inner) stride decomposition.
// Requirements relied on by call sites: K % 16 == 0, N % 128 == 0,
// lda/ldb multiples of 4 (16B-aligned rows).
template <bool TRANS_B>
__global__ __launch_bounds__(256) void sgemm_kernel(
    const float* __restrict__ A, long lda,
    const float* __restrict__ B, long ldb,
    float* __restrict__ C, long ldc,
    int M, int N, int Kd,
    const float* __restrict__ bias,
    const int* __restrict__ mPtr,
    const int* __restrict__ idxA,
    const int* __restrict__ idxC,
    int innerCnt,
    long aInner, long aOuter,
    long bInner, long bOuter,
    long cInner, long cOuter)
{
    int z  = blockIdx.z;
    int zo = z / innerCnt, zi = z - zo * innerCnt;
    A += (long)zo * aOuter + (long)zi * aInner;
    B += (long)zo * bOuter + (long)zi * bInner;
    C += (long)zo * cOuter + (long)zi * cInner;

    if (mPtr) M = *mPtr;
    int m0 = blockIdx.y * 128;
    int n0 = blockIdx.x * 128;
    if (m0 >= M) return;

    __shared__ float As[16][128];
    __shared__ float Bs[16][128];

    int tid = threadIdx.x;
    int tx  = tid & 15;       // 0..15 -> N
    int ty  = tid >> 4;       // 0..15 -> M

    float acc[8][8];
#pragma unroll
    for (int i = 0; i < 8; ++i)
#pragma unroll
        for (int j = 0; j < 8; ++j) acc[i][j] = 0.f;

    // A-load mapping: 2 threads per row, 8 consecutive k each (2x float4)
    int arow_l = tid >> 1;          // 0..127
    int ak0    = (tid & 1) * 8;     // 0 or 8
    int grow   = m0 + arow_l;
    bool aval  = grow < M;
    long arowIdx = 0;
    if (aval) arowIdx = idxA ? (long)idxA[grow] : (long)grow;
    const float* aBase = A + arowIdx * lda + ak0;

    for (int kk = 0; kk < Kd; kk += 16) {
        // ---- load A tile (k-major in smem) ----
        float4 a0, a1;
        if (aval) {
            a0 = *reinterpret_cast<const float4*>(aBase + kk);
            a1 = *reinterpret_cast<const float4*>(aBase + kk + 4);
        } else {
            a0 = make_float4(0.f, 0.f, 0.f, 0.f);
            a1 = a0;
        }
        As[ak0 + 0][arow_l] = a0.x;  As[ak0 + 1][arow_l] = a0.y;
        As[ak0 + 2][arow_l] = a0.z;  As[ak0 + 3][arow_l] = a0.w;
        As[ak0 + 4][arow_l] = a1.x;  As[ak0 + 5][arow_l] = a1.y;
        As[ak0 + 6][arow_l] = a1.z;  As[ak0 + 7][arow_l] = a1.w;

        // ---- load B tile ----
        if (TRANS_B) {
            int bc  = tid >> 1;            // n-col within tile 0..127
            int bk0 = (tid & 1) * 8;       // 0 or 8
            const float* bRow = B + (long)(n0 + bc) * ldb + bk0;
            float4 b0 = *reinterpret_cast<const float4*>(bRow + kk);
            float4 b1 = *reinterpret_cast<const float4*>(bRow + kk + 4);
            Bs[bk0 + 0][bc] = b0.x;  Bs[bk0 + 1][bc] = b0.y;
            Bs[bk0 + 2][bc] = b0.z;  Bs[bk0 + 3][bc] = b0.w;
            Bs[bk0 + 4][bc] = b1.x;  Bs[bk0 + 5][bc] = b1.y;
            Bs[bk0 + 6][bc] = b1.z;  Bs[bk0 + 7][bc] = b1.w;
        } else {
            int bk = tid >> 4;             // 0..15
            int bn = (tid & 15) * 8;       // 0..120
            const float* bp = B + (long)(kk + bk) * ldb + n0 + bn;
            float4 b0 = *reinterpret_cast<const float4*>(bp);
            float4 b1 = *reinterpret_cast<const float4*>(bp + 4);
            *reinterpret_cast<float4*>(&Bs[bk][bn])     = b0;
            *reinterpret_cast<float4*>(&Bs[bk][bn + 4]) = b1;
        }
        __syncthreads();

#pragma unroll
        for (int k = 0; k < 16; ++k) {
            float a[8], b[8];
#pragma unroll
            for (int i = 0; i < 8; ++i) a[i] = As[k][ty + i * 16];
#pragma unroll
            for (int j = 0; j < 8; ++j) b[j] = Bs[k][tx + j * 16];
#pragma unroll
            for (int i = 0; i < 8; ++i)
#pragma unroll
                for (int j = 0; j < 8; ++j)
                    acc[i][j] = fmaf(a[i], b[j], acc[i][j]);
        }
        __syncthreads();
    }

#pragma unroll
    for (int i = 0; i < 8; ++i) {
        int r = m0 + ty + i * 16;
        if (r >= M) continue;
        long cr = idxC ? (long)idxC[r] : (long)r;
#pragma unroll
        for (int j = 0; j < 8; ++j) {
            int c = n0 + tx + j * 16;
            if (c < N) {
                float v = acc[i][j];
                if (bias) v += bias[c];
                C[cr * ldc + c] = v;
            }
        }
    }
}

// ---------------- small kernels ----------------
__global__ void rmsnorm_kernel(const float* __restrict__ x,
                               const float* __restrict__ w,
                               float* __restrict__ out)
{
    int t = blockIdx.x;
    const float* xr = x + (long)t * Dd;
    float ss = 0.f;
    for (int d = threadIdx.x; d < Dd; d += 256) { float v = xr[d]; ss += v * v; }
    __shared__ float red[256];
    red[threadIdx.x] = ss; __syncthreads();
    for (int s = 128; s > 0; s >>= 1) {
        if (threadIdx.x < s) red[threadIdx.x] += red[threadIdx.x + s];
        __syncthreads();
    }
    float inv = rsqrtf(red[0] / (float)Dd + EPSf);
    for (int d = threadIdx.x; d < Dd; d += 256)
        out[(long)t * Dd + d] = xr[d] * inv * w[d];
}

__global__ void rope_kernel(float* __restrict__ q, float* __restrict__ k,
                            const int* __restrict__ pos_ids,
                            const float* __restrict__ sin_t,
                            const float* __restrict__ cos_t)
{
    int bh = blockIdx.x;           // Tt * Hh blocks
    int t  = bh / Hh, h = bh % Hh;
    int d  = threadIdx.x;          // 128 threads
    int p  = pos_ids[t];
    float c = cos_t[(long)p * DHh + d];
    float s = sin_t[(long)p * DHh + d];
    long base = (long)t * HD + (long)h * DHh;
    float qv = q[base + d], kv = k[base + d];
    int  pd  = (d < 64) ? d + 64 : d - 64;
    float sg = (d < 64) ? -1.f : 1.f;
    float qp = q[base + pd] * sg;
    float kp = k[base + pd] * sg;
    __syncthreads();
    q[base + d] = qv * c + qp * s;
    k[base + d] = kv * c + kp * s;
}

__global__ void softmax_kernel(float* __restrict__ scores,
                               const int* __restrict__ amask)
{
    long row = blockIdx.x;                 // Bb*Hh*Ss rows of length Ss
    int qp = (int)(row % Ss);
    int b  = (int)(row / ((long)Hh * Ss));
    float* p = scores + row * Ss;
    const int* am = amask + (long)b * Ss;

    float vals[4];
    float mx = -1e30f;
#pragma unroll
    for (int i = 0; i < 4; ++i) {
        int kpos = threadIdx.x + i * 256;
        float v = p[kpos] * SCALEf;
        bool ok = (kpos <= qp) && (am[kpos] > 0);
        vals[i] = ok ? v : -1e30f;
        mx = fmaxf(mx, vals[i]);
    }
    __shared__ float red[256];
    red[threadIdx.x] = mx; __syncthreads();
    for (int s = 128; s > 0; s >>= 1) {
        if (threadIdx.x < s) red[threadIdx.x] = fmaxf(red[threadIdx.x], red[threadIdx.x + s]);
        __syncthreads();
    }
    mx = red[0]; __syncthreads();

    float sum = 0.f;
#pragma unroll
    for (int i = 0; i < 4; ++i) {
        vals[i] = (vals[i] > -1e29f) ? expf(vals[i] - mx) : 0.f;
        sum += vals[i];
    }
    red[threadIdx.x] = sum; __syncthreads();
    for (int s = 128; s > 0; s >>= 1) {
        if (threadIdx.x < s) red[threadIdx.x] += red[threadIdx.x + s];
        __syncthreads();
    }
    float tot = red[0];
    float inv = (tot > 0.f) ? 1.f / tot : 0.f;
#pragma unroll
    for (int i = 0; i < 4; ++i) {
        int kpos = threadIdx.x + i * 256;
        p[kpos] = vals[i] * inv;
    }
}

__global__ void add_kernel(const float4* __restrict__ a,
                           const float4* __restrict__ b,
                           float4* __restrict__ out)
{
    long i = (long)blockIdx.x * 256 + threadIdx.x;
    float4 av = a[i], bv = b[i];
    out[i] = make_float4(av.x + bv.x, av.y + bv.y, av.z + bv.z, av.w + bv.w);
}

__global__ void zero_cnt_kernel(int* cnt)
{
    if (threadIdx.x < Ee) cnt[threadIdx.x] = 0;
}

__global__ void router_kernel(const float* __restrict__ h2,
                              const float* __restrict__ rw,
                              const float* __restrict__ sgw,
                              float* __restrict__ topv,
                              float* __restrict__ sgate,
                              int* __restrict__ cnt,
                              int* __restrict__ tokA,
                              int* __restrict__ dstC)
{
    int t = blockIdx.x;
    const float* x = h2 + (long)t * Dd;
    float acc[9];
#pragma unroll
    for (int e = 0; e < 9; ++e) acc[e] = 0.f;
    for (int d = threadIdx.x; d < Dd; d += 256) {
        float xv = x[d];
#pragma unroll
        for (int e = 0; e < 8; ++e) acc[e] += xv * rw[(long)d * Ee + e];
        acc[8] += xv * sgw[d];
    }
    __shared__ float s[9][256];
#pragma unroll
    for (int e = 0; e < 9; ++e) s[e][threadIdx.x] = acc[e];
    __syncthreads();
    for (int st = 128; st > 0; st >>= 1) {
        if (threadIdx.x < st)
#pragma unroll
            for (int e = 0; e < 9; ++e) s[e][threadIdx.x] += s[e][threadIdx.x + st];
        __syncthreads();
    }
    if (threadIdx.x == 0) {
        float lg[8];
        float m = -1e30f;
#pragma unroll
        for (int e = 0; e < 8; ++e) { lg[e] = s[e][0]; m = fmaxf(m, lg[e]); }
        float sum = 0.f;
#pragma unroll
        for (int e = 0; e < 8; ++e) { lg[e] = expf(lg[e] - m); sum += lg[e]; }
        float invs = 1.f / sum;
#pragma unroll
        for (int e = 0; e < 8; ++e) lg[e] *= invs;
        int i1 = 0;
#pragma unroll
        for (int e = 1; e < 8; ++e) if (lg[e] > lg[i1]) i1 = e;
        int i2 = (i1 == 0) ? 1 : 0;
#pragma unroll
        for (int e = 0; e < 8; ++e) if (e != i1 && lg[e] > lg[i2]) i2 = e;
        int es[2] = { i1, i2 };
#pragma unroll
        for (int kk = 0; kk < 2; ++kk) {
            int e = es[kk];
            int slot = atomicAdd(&cnt[e], 1);
            tokA[e * Tt + slot] = t;
            dstC[e * Tt + slot] = t * 2 + kk;
            topv[t * 2 + kk] = lg[e];
        }
        sgate[t] = 1.f / (1.f + expf(-s[8][0]));
    }
}

__global__ void act_moe_kernel(float4* __restrict__ g,
                               const float4* __restrict__ u,
                               const float* __restrict__ topv)
{
    long i4 = (long)blockIdx.x * 256 + threadIdx.x;
    if (i4 >= GSZ / 4) return;
    long t2 = (i4 * 4) / Ii;          // slot row (Ii % 4 == 0)
    float tv = topv[t2];
    float4 gv = g[i4], uv = u[i4];
    gv.x = gv.x / (1.f + expf(-gv.x)) * uv.x * tv;
    gv.y = gv.y / (1.f + expf(-gv.y)) * uv.y * tv;
    gv.z = gv.z / (1.f + expf(-gv.z)) * uv.z * tv;
    gv.w = gv.w / (1.f + expf(-gv.w)) * uv.w * tv;
    g[i4] = gv;
}

__global__ void act_shared_kernel(float4* __restrict__ g,
                                  const float4* __restrict__ u)
{
    long i4 = (long)blockIdx.x * 256 + threadIdx.x;
    if (i4 >= SGSZ / 4) return;
    float4 gv = g[i4], uv = u[i4];
    gv.x = gv.x / (1.f + expf(-gv.x)) * uv.x;
    gv.y = gv.y / (1.f + expf(-gv.y)) * uv.y;
    gv.z = gv.z / (1.f + expf(-gv.z)) * uv.z;
    gv.w = gv.w / (1.f + expf(-gv.w)) * uv.w;
    g[i4] = gv;
}

__global__ void combine_kernel(const float4* __restrict__ res,
                               const float4* __restrict__ moeslot,
                               const float4* __restrict__ sh,
                               const float* __restrict__ sgate,
                               float4* __restrict__ out)
{
    long i4 = (long)blockIdx.x * 256 + threadIdx.x;   // TD/4 elements
    long t  = (i4 * 4) / Dd;
    long d4 = i4 - t * (Dd / 4);
    float4 m0 = moeslot[(t * 2)     * (long)(Dd / 4) + d4];
    float4 m1 = moeslot[(t * 2 + 1) * (long)(Dd / 4) + d4];
    float4 rv = res[i4], sv = sh[i4];
    float sg = sgate[t];
    out[i4] = make_float4(rv.x + m0.x + m1.x + sg * sv.x,
                          rv.y + m0.y + m1.y + sg * sv.y,
                          rv.z + m0.z + m1.z + sg * sv.z,
                          rv.w + m0.w + m1.w + sg * sv.w);
}

// ---------------- host launchers ----------------
static void gemm(bool transB,
                 const float* A, long lda, const float* B, long ldb,
                 float* C, long ldc, int M, int N, int K,
                 const float* bias, const int* mPtr,
                 const int* idxA, const int* idxC,
                 int batch = 1, int innerCnt = 1,
                 long aI = 0, long aO = 0, long bI = 0, long bO = 0,
                 long cI = 0, long cO = 0)
{
    dim3 grid((N + 127) / 128, (M + 127) / 128, batch);
    if (transB)
        sgemm_kernel<true><<<grid, 256>>>(A, lda, B, ldb, C, ldc, M, N, K,
                                          bias, mPtr, idxA, idxC, innerCnt,
                                          aI, aO, bI, bO, cI, cO);
    else
        sgemm_kernel<false><<<grid, 256>>>(A, lda, B, ldb, C, ldc, M, N, K,
                                           bias, mPtr, idxA, idxC, innerCnt,
                                           aI, aO, bI, bO, cI, cO);
}

extern "C" void kernel_launch(void* const* d_in, const int* in_sizes, int n_in,
                              void* d_out, int out_size)
{
    const float* x      = (const float*)d_in[0];
    const int*   pos    = (const int*)  d_in[1];
    const int*   amask  = (const int*)  d_in[2];
    const float* sin_t  = (const float*)d_in[3];
    const float* cos_t  = (const float*)d_in[4];
    const float* ln1    = (const float*)d_in[5];
    const float* ln2    = (const float*)d_in[6];
    const float* qw     = (const float*)d_in[7];
    const float* qb     = (const float*)d_in[8];
    const float* kw     = (const float*)d_in[9];
    const float* kb     = (const float*)d_in[10];
    const float* vw     = (const float*)d_in[11];
    const float* vb     = (const float*)d_in[12];
    const float* ow     = (const float*)d_in[13];
    const float* rtw    = (const float*)d_in[14];
    const float* egw    = (const float*)d_in[15];
    const float* euw    = (const float*)d_in[16];
    const float* edw    = (const float*)d_in[17];
    const float* sgw    = (const float*)d_in[18];
    const float* suw    = (const float*)d_in[19];
    const float* sdw    = (const float*)d_in[20];
    const float* shgw   = (const float*)d_in[21];
    float* out = (float*)d_out;

    float* buf;  cudaGetSymbolAddress((void**)&buf,  g_buf);
    int*   cnt;  cudaGetSymbolAddress((void**)&cnt,  g_cnt);
    int*   tokA; cudaGetSymbolAddress((void**)&tokA, g_tokA);
    int*   dstC; cudaGetSymbolAddress((void**)&dstC, g_dstC);

    // 1. rmsnorm 1
    rmsnorm_kernel<<<Tt, 256>>>(x, ln1, buf + O_H1);

    // 2. QKV projections (+bias)
    gemm(false, buf + O_H1, Dd, qw, HD, buf + O_Q, HD, Tt, HD, Dd, qb, nullptr, nullptr, nullptr);
    gemm(false, buf + O_H1, Dd, kw, HD, buf + O_K, HD, Tt, HD, Dd, kb, nullptr, nullptr, nullptr);
    gemm(false, buf + O_H1, Dd, vw, HD, buf + O_V, HD, Tt, HD, Dd, vb, nullptr, nullptr, nullptr);

    // 3. RoPE on q, k
    rope_kernel<<<Tt * Hh, DHh>>>(buf + O_Q, buf + O_K, pos, sin_t, cos_t);

    // 4. scores = Q @ K^T  (batched over B*H)
    gemm(true, buf + O_Q, HD, buf + O_K, HD, buf + O_SC, Ss,
         Ss, Ss, DHh, nullptr, nullptr, nullptr, nullptr,
         Bb * Hh, Hh,
         /*aI*/ DHh, /*aO*/ (long)Ss * HD,
         /*bI*/ DHh, /*bO*/ (long)Ss * HD,
         /*cI*/ (long)Ss * Ss, /*cO*/ (long)Hh * Ss * Ss);

    // 5. masked causal softmax (in place)
    softmax_kernel<<<Bb * Hh * Ss, 256>>>(buf + O_SC, amask);

    // 6. attn = P @ V
    gemm(false, buf + O_SC, Ss, buf + O_V, HD, buf + O_ATT, HD,
         Ss, DHh, Ss, nullptr, nullptr, nullptr, nullptr,
         Bb * Hh, Hh,
         /*aI*/ (long)Ss * Ss, /*aO*/ (long)Hh * Ss * Ss,
         /*bI*/ DHh, /*bO*/ (long)Ss * HD,
         /*cI*/ DHh, /*cO*/ (long)Ss * HD);

    // 7. O projection (reuse O_H1 as scratch)
    gemm(false, buf + O_ATT, HD, ow, Dd, buf + O_H1, Dd, Tt, Dd, HD,
         nullptr, nullptr, nullptr, nullptr);

    // 8. residual: h = x + attn_out
    add_kernel<<<(int)(TD / 4 / 256), 256>>>((const float4*)x,
                                             (const float4*)(buf + O_H1),
                                             (float4*)(buf + O_RES));

    // 9. rmsnorm 2
    rmsnorm_kernel<<<Tt, 256>>>(buf + O_RES, ln2, buf + O_H2);

    // 10. routing (+ shared gate)
    zero_cnt_kernel<<<1, 32>>>(cnt);
    router_kernel<<<Tt, 256>>>(buf + O_H2, rtw, shgw,
                               buf + O_TOPV, buf + O_SGATE, cnt, tokA, dstC);

    // 11. expert gate/up GEMMs (gathered tokens, scattered to (t,k) rows)
    for (int e = 0; e < Ee; ++e) {
        gemm(false, buf + O_H2, Dd, egw + (long)e * Dd * Ii, Ii,
             buf + O_G, Ii, Tt, Ii, Dd,
             nullptr, cnt + e, tokA + e * Tt, dstC + e * Tt);
        gemm(false, buf + O_H2, Dd, euw + (long)e * Dd * Ii, Ii,
             buf + O_U, Ii, Tt, Ii, Dd,
             nullptr, cnt + e, tokA + e * Tt, dstC + e * Tt);
    }

    // 12. act = silu(g) * u * topv
    act_moe_kernel<<<(int)((GSZ / 4 + 255) / 256), 256>>>(
        (float4*)(buf + O_G), (const float4*)(buf + O_U), buf + O_TOPV);

    // 13. expert down GEMMs -> per-(t,k) slot
    for (int e = 0; e < Ee; ++e) {
        gemm(false, buf + O_G, Ii, edw + (long)e * Ii * Dd, Dd,
             buf + O_MOE, Dd, Tt, Dd, Ii,
             nullptr, cnt + e, dstC + e * Tt, dstC + e * Tt);
    }

    // 14. shared expert
    gemm(false, buf + O_H2, Dd, sgw, ISs, buf + O_SG, ISs, Tt, ISs, Dd,
         nullptr, nullptr, nullptr, nullptr);
    gemm(false, buf + O_H2, Dd, suw, ISs, buf + O_SU, ISs, Tt, ISs, Dd,
         nullptr, nullptr, nullptr, nullptr);
    act_shared_kernel<<<(int)((SGSZ / 4 + 255) / 256), 256>>>(
        (float4*)(buf + O_SG), (const float4*)(buf + O_SU));
    gemm(false, buf + O_SG, ISs, sdw, Dd, buf + O_SH, Dd, Tt, Dd, ISs,
         nullptr, nullptr, nullptr, nullptr);

    // 15. final combine
    combine_kernel<<<(int)(TD / 4 / 256), 256>>>(
        (const float4*)(buf + O_RES), (const float4*)(buf + O_MOE),
        (const float4*)(buf + O_SH), buf + O_SGATE, (float4*)out);
}

// round 9
// speedup vs baseline: 3.0424x; 3.0424x over previous
#include <cuda_runtime.h>
#include <math.h>

// ---------------- problem constants ----------------
constexpr int Bb  = 2;
constexpr int Ss  = 1024;
constexpr int Dd  = 2048;
constexpr int Hh  = 16;
constexpr int DHh = 128;
constexpr int HD  = Hh * DHh;     // 2048
constexpr int Ee  = 8;
constexpr int KK  = 2;
constexpr int Ii  = 1408;
constexpr int ISs = 5632;
constexpr int Tt  = Bb * Ss;      // 2048 tokens
constexpr float EPSf   = 1e-6f;
constexpr float SCALEf = 0.08838834764831845f;   // 1/sqrt(128)

// ---------------- scratch layout (single __device__ arena) ----------------
constexpr long TD   = (long)Tt * Dd;
constexpr long SCSZ = (long)Bb * Hh * Ss * Ss;
constexpr long GSZ  = (long)Tt * KK * Ii;
constexpr long MSZ  = (long)Tt * KK * Dd;
constexpr long SGSZ = (long)Tt * ISs;

constexpr long O_H1   = 0;
constexpr long O_Q    = O_H1  + TD;
constexpr long O_K    = O_Q   + TD;
constexpr long O_V    = O_K   + TD;
constexpr long O_SC   = O_V   + TD;
constexpr long O_ATT  = O_SC  + SCSZ;
constexpr long O_RES  = O_ATT + TD;
constexpr long O_H2   = O_RES + TD;
constexpr long O_G    = O_H2  + TD;
constexpr long O_U    = O_G   + GSZ;
constexpr long O_MOE  = O_U   + GSZ;
constexpr long O_SG   = O_MOE + MSZ;
constexpr long O_SU   = O_SG  + SGSZ;
constexpr long O_SH   = O_SU  + SGSZ;
constexpr long O_TOPV = O_SH  + TD;
constexpr long O_SGATE= O_TOPV+ (long)Tt * KK;
constexpr long GBUF_TOTAL = O_SGATE + Tt;

__device__ float g_buf[GBUF_TOTAL];
__device__ int   g_cnt[Ee];
__device__ int   g_tokA[Ee * Tt];
__device__ int   g_dstC[Ee * Tt];

// ---------------- tf32 helpers ----------------
__device__ __forceinline__ unsigned f2t(float f) {
    unsigned u; asm("cvt.rna.tf32.f32 %0, %1;" : "=r"(u) : "f"(f)); return u;
}

#define MMA_TF32(c, a, b0, b1)                                              \
    asm volatile(                                                           \
        "mma.sync.aligned.m16n8k8.row.col.f32.tf32.tf32.f32 "               \
        "{%0,%1,%2,%3}, {%4,%5,%6,%7}, {%8,%9}, {%0,%1,%2,%3};"             \
        : "+f"(c[0]), "+f"(c[1]), "+f"(c[2]), "+f"(c[3])                    \
        : "r"(a[0]), "r"(a[1]), "r"(a[2]), "r"(a[3]), "r"(b0), "r"(b1))

// ---------------- generic tf32 tensor-core GEMM ----------------
// C[M,N] = A[M,K] * B  (B row-major KxN, or TRANS_B: B row-major NxK -> A*B^T)
// 128x128 CTA tile, BK=16, 8 warps (4x2), warp tile 32x64 via m16n8k8 atoms.
// Optional: bias, device-side M (mPtr), A row gather (idxA), C row scatter
// (idxC), batching via blockIdx.z (outer/inner stride decomposition).
// Requirements: K % 16 == 0, N % 128 == 0, rows 16B-aligned.
template <bool TRANS_B>
__global__ __launch_bounds__(256) void tgemm_kernel(
    const float* __restrict__ A, long lda,
    const float* __restrict__ B, long ldb,
    float* __restrict__ C, long ldc,
    int M, int N, int Kd,
    const float* __restrict__ bias,
    const int* __restrict__ mPtr,
    const int* __restrict__ idxA,
    const int* __restrict__ idxC,
    int innerCnt,
    long aInner, long aOuter,
    long bInner, long bOuter,
    long cInner, long cOuter)
{
    int z  = blockIdx.z;
    int zo = z / innerCnt, zi = z - zo * innerCnt;
    A += (long)zo * aOuter + (long)zi * aInner;
    B += (long)zo * bOuter + (long)zi * bInner;
    C += (long)zo * cOuter + (long)zi * cInner;

    if (mPtr) M = *mPtr;
    int m0 = blockIdx.y * 128;
    int n0 = blockIdx.x * 128;
    if (m0 >= M) return;

    // A m-major (row pad 20 floats -> conflict-free frag loads)
    // B k-major (row pad 136 floats -> conflict-free frag loads)
    __shared__ unsigned As[128][20];
    __shared__ unsigned Bs[16][136];

    int tid  = threadIdx.x;
    int lane = tid & 31;
    int wid  = tid >> 5;
    int quad = lane >> 2, qid = lane & 3;
    int wm   = (wid & 3) * 32;    // warp m-offset in tile
    int wn   = (wid >> 2) * 64;   // warp n-offset in tile

    float acc[2][8][4];
#pragma unroll
    for (int mt = 0; mt < 2; ++mt)
#pragma unroll
        for (int nt = 0; nt < 8; ++nt)
#pragma unroll
            for (int r = 0; r < 4; ++r) acc[mt][nt][r] = 0.f;

    // A global mapping: 2 threads per row, 8 consecutive k each
    int arow = tid >> 1, ak0 = (tid & 1) * 8;
    int grow = m0 + arow;
    bool aval = grow < M;
    long arowIdx = 0;
    if (aval) arowIdx = idxA ? (long)idxA[grow] : (long)grow;
    const float* aPtr = A + arowIdx * lda + ak0;

    // B global mapping
    const float* bPtr;
    int btr_c = 0, btr_k0 = 0, bnr_k = 0, bnr_n = 0;
    if (TRANS_B) {
        btr_c = tid >> 1; btr_k0 = (tid & 1) * 8;
        bPtr = B + (long)(n0 + btr_c) * ldb + btr_k0;
    } else {
        bnr_k = tid >> 4; bnr_n = (tid & 15) * 8;
        bPtr = B + (long)bnr_k * ldb + n0 + bnr_n;
    }

    float4 ra0 = make_float4(0.f,0.f,0.f,0.f), ra1 = ra0, rb0 = ra0, rb1 = ra0;

    // prefetch tile 0
    if (aval) {
        ra0 = *reinterpret_cast<const float4*>(aPtr);
        ra1 = *reinterpret_cast<const float4*>(aPtr + 4);
    }
    rb0 = *reinterpret_cast<const float4*>(bPtr);
    rb1 = *reinterpret_cast<const float4*>(bPtr + 4);

    int nk = Kd >> 4;
    for (int it = 0; it < nk; ++it) {
        // ---- stage prefetched regs into smem (cvt to tf32) ----
        {
            uint4 pa0 = make_uint4(f2t(ra0.x), f2t(ra0.y), f2t(ra0.z), f2t(ra0.w));
            uint4 pa1 = make_uint4(f2t(ra1.x), f2t(ra1.y), f2t(ra1.z), f2t(ra1.w));
            *reinterpret_cast<uint4*>(&As[arow][ak0])     = pa0;
            *reinterpret_cast<uint4*>(&As[arow][ak0 + 4]) = pa1;
            if (TRANS_B) {
                Bs[btr_k0 + 0][btr_c] = f2t(rb0.x);
                Bs[btr_k0 + 1][btr_c] = f2t(rb0.y);
                Bs[btr_k0 + 2][btr_c] = f2t(rb0.z);
                Bs[btr_k0 + 3][btr_c] = f2t(rb0.w);
                Bs[btr_k0 + 4][btr_c] = f2t(rb1.x);
                Bs[btr_k0 + 5][btr_c] = f2t(rb1.y);
                Bs[btr_k0 + 6][btr_c] = f2t(rb1.z);
                Bs[btr_k0 + 7][btr_c] = f2t(rb1.w);
            } else {
                uint4 pb0 = make_uint4(f2t(rb0.x), f2t(rb0.y), f2t(rb0.z), f2t(rb0.w));
                uint4 pb1 = make_uint4(f2t(rb1.x), f2t(rb1.y), f2t(rb1.z), f2t(rb1.w));
                *reinterpret_cast<uint4*>(&Bs[bnr_k][bnr_n])     = pb0;
                *reinterpret_cast<uint4*>(&Bs[bnr_k][bnr_n + 4]) = pb1;
            }
        }
        __syncthreads();

        // ---- prefetch next tile (overlaps with MMA below) ----
        if (it + 1 < nk) {
            long kk = (long)(it + 1) * 16;
            if (aval) {
                ra0 = *reinterpret_cast<const float4*>(aPtr + kk);
                ra1 = *reinterpret_cast<const float4*>(aPtr + kk + 4);
            }
            if (TRANS_B) {
                rb0 = *reinterpret_cast<const float4*>(bPtr + kk);
                rb1 = *reinterpret_cast<const float4*>(bPtr + kk + 4);
            } else {
                rb0 = *reinterpret_cast<const float4*>(bPtr + kk * ldb);
                rb1 = *reinterpret_cast<const float4*>(bPtr + kk * ldb + 4);
            }
        }

        // ---- MMA on current tile ----
#pragma unroll
        for (int ks = 0; ks < 2; ++ks) {
            int k0 = ks * 8;
            unsigned a[2][4];
#pragma unroll
            for (int mt = 0; mt < 2; ++mt) {
                int r = wm + mt * 16 + quad;
                a[mt][0] = As[r][k0 + qid];
                a[mt][1] = As[r + 8][k0 + qid];
                a[mt][2] = As[r][k0 + qid + 4];
                a[mt][3] = As[r + 8][k0 + qid + 4];
            }
#pragma unroll
            for (int nt = 0; nt < 8; ++nt) {
                int n = wn + nt * 8 + quad;
                unsigned b0 = Bs[k0 + qid][n];
                unsigned b1 = Bs[k0 + qid + 4][n];
                MMA_TF32(acc[0][nt], a[0], b0, b1);
                MMA_TF32(acc[1][nt], a[1], b0, b1);
            }
        }
        __syncthreads();
    }

    // ---- epilogue ----
#pragma unroll
    for (int mt = 0; mt < 2; ++mt) {
#pragma unroll
        for (int half = 0; half < 2; ++half) {
            int r = m0 + wm + mt * 16 + quad + half * 8;
            if (r >= M) continue;
            long cr = idxC ? (long)idxC[r] : (long)r;
            float* cRow = C + cr * ldc;
#pragma unroll
            for (int nt = 0; nt < 8; ++nt) {
                int c = n0 + wn + nt * 8 + 2 * qid;
                float v0 = acc[mt][nt][half * 2 + 0];
                float v1 = acc[mt][nt][half * 2 + 1];
                if (bias) { v0 += bias[c]; v1 += bias[c + 1]; }
                *reinterpret_cast<float2*>(cRow + c) = make_float2(v0, v1);
            }
        }
    }
}

// ---------------- small kernels ----------------
__global__ void rmsnorm_kernel(const float* __restrict__ x,
                               const float* __restrict__ w,
                               float* __restrict__ out)
{
    int t = blockIdx.x;
    const float* xr = x + (long)t * Dd;
    float ss = 0.f;
    for (int d = threadIdx.x; d < Dd; d += 256) { float v = xr[d]; ss += v * v; }
    __shared__ float red[256];
    red[threadIdx.x] = ss; __syncthreads();
    for (int s = 128; s > 0; s >>= 1) {
        if (threadIdx.x < s) red[threadIdx.x] += red[threadIdx.x + s];
        __syncthreads();
    }
    float inv = rsqrtf(red[0] / (float)Dd + EPSf);
    for (int d = threadIdx.x; d < Dd; d += 256)
        out[(long)t * Dd + d] = xr[d] * inv * w[d];
}

__global__ void rope_kernel(float* __restrict__ q, float* __restrict__ k,
                            const int* __restrict__ pos_ids,
                            const float* __restrict__ sin_t,
                            const float* __restrict__ cos_t)
{
    int bh = blockIdx.x;           // Tt * Hh blocks
    int t  = bh / Hh, h = bh % Hh;
    int d  = threadIdx.x;          // 128 threads
    int p  = pos_ids[t];
    float c = cos_t[(long)p * DHh + d];
    float s = sin_t[(long)p * DHh + d];
    long base = (long)t * HD + (long)h * DHh;
    float qv = q[base + d], kv = k[base + d];
    int  pd  = (d < 64) ? d + 64 : d - 64;
    float sg = (d < 64) ? -1.f : 1.f;
    float qp = q[base + pd] * sg;
    float kp = k[base + pd] * sg;
    __syncthreads();
    q[base + d] = qv * c + qp * s;
    k[base + d] = kv * c + kp * s;
}

__global__ void softmax_kernel(float* __restrict__ scores,
                               const int* __restrict__ amask)
{
    long row = blockIdx.x;                 // Bb*Hh*Ss rows of length Ss
    int qp = (int)(row % Ss);
    int b  = (int)(row / ((long)Hh * Ss));
    float* p = scores + row * Ss;
    const int* am = amask + (long)b * Ss;

    float vals[4];
    float mx = -1e30f;
#pragma unroll
    for (int i = 0; i < 4; ++i) {
        int kpos = threadIdx.x + i * 256;
        float v = p[kpos] * SCALEf;
        bool ok = (kpos <= qp) && (am[kpos] > 0);
        vals[i] = ok ? v : -1e30f;
        mx = fmaxf(mx, vals[i]);
    }
    __shared__ float red[256];
    red[threadIdx.x] = mx; __syncthreads();
    for (int s = 128; s > 0; s >>= 1) {
        if (threadIdx.x < s) red[threadIdx.x] = fmaxf(red[threadIdx.x], red[threadIdx.x + s]);
        __syncthreads();
    }
    mx = red[0]; __syncthreads();

    float sum = 0.f;
#pragma unroll
    for (int i = 0; i < 4; ++i) {
        vals[i] = (vals[i] > -1e29f) ? expf(vals[i] - mx) : 0.f;
        sum += vals[i];
    }
    red[threadIdx.x] = sum; __syncthreads();
    for (int s = 128; s > 0; s >>= 1) {
        if (threadIdx.x < s) red[threadIdx.x] += red[threadIdx.x + s];
        __syncthreads();
    }
    float tot = red[0];
    float inv = (tot > 0.f) ? 1.f / tot : 0.f;
#pragma unroll
    for (int i = 0; i < 4; ++i) {
        int kpos = threadIdx.x + i * 256;
        p[kpos] = vals[i] * inv;
    }
}

__global__ void add_kernel(const float4* __restrict__ a,
                           const float4* __restrict__ b,
                           float4* __restrict__ out)
{
    long i = (long)blockIdx.x * 256 + threadIdx.x;
    float4 av = a[i], bv = b[i];
    out[i] = make_float4(av.x + bv.x, av.y + bv.y, av.z + bv.z, av.w + bv.w);
}

__global__ void zero_cnt_kernel(int* cnt)
{
    if (threadIdx.x < Ee) cnt[threadIdx.x] = 0;
}

__global__ void router_kernel(const float* __restrict__ h2,
                              const float* __restrict__ rw,
                              const float* __restrict__ sgw,
                              float* __restrict__ topv,
                              float* __restrict__ sgate,
                              int* __restrict__ cnt,
                              int* __restrict__ tokA,
                              int* __restrict__ dstC)
{
    int t = blockIdx.x;
    const float* x = h2 + (long)t * Dd;
    float acc[9];
#pragma unroll
    for (int e = 0; e < 9; ++e) acc[e] = 0.f;
    for (int d = threadIdx.x; d < Dd; d += 256) {
        float xv = x[d];
#pragma unroll
        for (int e = 0; e < 8; ++e) acc[e] += xv * rw[(long)d * Ee + e];
        acc[8] += xv * sgw[d];
    }
    __shared__ float s[9][256];
#pragma unroll
    for (int e = 0; e < 9; ++e) s[e][threadIdx.x] = acc[e];
    __syncthreads();
    for (int st = 128; st > 0; st >>= 1) {
        if (threadIdx.x < st)
#pragma unroll
            for (int e = 0; e < 9; ++e) s[e][threadIdx.x] += s[e][threadIdx.x + st];
        __syncthreads();
    }
    if (threadIdx.x == 0) {
        float lg[8];
        float m = -1e30f;
#pragma unroll
        for (int e = 0; e < 8; ++e) { lg[e] = s[e][0]; m = fmaxf(m, lg[e]); }
        float sum = 0.f;
#pragma unroll
        for (int e = 0; e < 8; ++e) { lg[e] = expf(lg[e] - m); sum += lg[e]; }
        float invs = 1.f / sum;
#pragma unroll
        for (int e = 0; e < 8; ++e) lg[e] *= invs;
        int i1 = 0;
#pragma unroll
        for (int e = 1; e < 8; ++e) if (lg[e] > lg[i1]) i1 = e;
        int i2 = (i1 == 0) ? 1 : 0;
#pragma unroll
        for (int e = 0; e < 8; ++e) if (e != i1 && lg[e] > lg[i2]) i2 = e;
        int es[2] = { i1, i2 };
#pragma unroll
        for (int kk = 0; kk < 2; ++kk) {
            int e = es[kk];
            int slot = atomicAdd(&cnt[e], 1);
            tokA[e * Tt + slot] = t;
            dstC[e * Tt + slot] = t * 2 + kk;
            topv[t * 2 + kk] = lg[e];
        }
        sgate[t] = 1.f / (1.f + expf(-s[8][0]));
    }
}

__global__ void act_moe_kernel(float4* __restrict__ g,
                               const float4* __restrict__ u,
                               const float* __restrict__ topv)
{
    long i4 = (long)blockIdx.x * 256 + threadIdx.x;
    if (i4 >= GSZ / 4) return;
    long t2 = (i4 * 4) / Ii;          // slot row (Ii % 4 == 0)
    float tv = topv[t2];
    float4 gv = g[i4], uv = u[i4];
    gv.x = gv.x / (1.f + expf(-gv.x)) * uv.x * tv;
    gv.y = gv.y / (1.f + expf(-gv.y)) * uv.y * tv;
    gv.z = gv.z / (1.f + expf(-gv.z)) * uv.z * tv;
    gv.w = gv.w / (1.f + expf(-gv.w)) * uv.w * tv;
    g[i4] = gv;
}

__global__ void act_shared_kernel(float4* __restrict__ g,
                                  const float4* __restrict__ u)
{
    long i4 = (long)blockIdx.x * 256 + threadIdx.x;
    if (i4 >= SGSZ / 4) return;
    float4 gv = g[i4], uv = u[i4];
    gv.x = gv.x / (1.f + expf(-gv.x)) * uv.x;
    gv.y = gv.y / (1.f + expf(-gv.y)) * uv.y;
    gv.z = gv.z / (1.f + expf(-gv.z)) * uv.z;
    gv.w = gv.w / (1.f + expf(-gv.w)) * uv.w;
    g[i4] = gv;
}

__global__ void combine_kernel(const float4* __restrict__ res,
                               const float4* __restrict__ moeslot,
                               const float4* __restrict__ sh,
                               const float* __restrict__ sgate,
                               float4* __restrict__ out)
{
    long i4 = (long)blockIdx.x * 256 + threadIdx.x;   // TD/4 elements
    long t  = (i4 * 4) / Dd;
    long d4 = i4 - t * (Dd / 4);
    float4 m0 = moeslot[(t * 2)     * (long)(Dd / 4) + d4];
    float4 m1 = moeslot[(t * 2 + 1) * (long)(Dd / 4) + d4];
    float4 rv = res[i4], sv = sh[i4];
    float sg = sgate[t];
    out[i4] = make_float4(rv.x + m0.x + m1.x + sg * sv.x,
                          rv.y + m0.y + m1.y + sg * sv.y,
                          rv.z + m0.z + m1.z + sg * sv.z,
                          rv.w + m0.w + m1.w + sg * sv.w);
}

// ---------------- host launchers ----------------
static void gemm(bool transB,
                 const float* A, long lda, const float* B, long ldb,
                 float* C, long ldc, int M, int N, int K,
                 const float* bias, const int* mPtr,
                 const int* idxA, const int* idxC,
                 int batch = 1, int innerCnt = 1,
                 long aI = 0, long aO = 0, long bI = 0, long bO = 0,
                 long cI = 0, long cO = 0)
{
    dim3 grid(N / 128, (M + 127) / 128, batch);
    if (transB)
        tgemm_kernel<true><<<grid, 256>>>(A, lda, B, ldb, C, ldc, M, N, K,
                                          bias, mPtr, idxA, idxC, innerCnt,
                                          aI, aO, bI, bO, cI, cO);
    else
        tgemm_kernel<false><<<grid, 256>>>(A, lda, B, ldb, C, ldc, M, N, K,
                                           bias, mPtr, idxA, idxC, innerCnt,
                                           aI, aO, bI, bO, cI, cO);
}

extern "C" void kernel_launch(void* const* d_in, const int* in_sizes, int n_in,
                              void* d_out, int out_size)
{
    const float* x      = (const float*)d_in[0];
    const int*   pos    = (const int*)  d_in[1];
    const int*   amask  = (const int*)  d_in[2];
    const float* sin_t  = (const float*)d_in[3];
    const float* cos_t  = (const float*)d_in[4];
    const float* ln1    = (const float*)d_in[5];
    const float* ln2    = (const float*)d_in[6];
    const float* qw     = (const float*)d_in[7];
    const float* qb     = (const float*)d_in[8];
    const float* kw     = (const float*)d_in[9];
    const float* kb     = (const float*)d_in[10];
    const float* vw     = (const float*)d_in[11];
    const float* vb     = (const float*)d_in[12];
    const float* ow     = (const float*)d_in[13];
    const float* rtw    = (const float*)d_in[14];
    const float* egw    = (const float*)d_in[15];
    const float* euw    = (const float*)d_in[16];
    const float* edw    = (const float*)d_in[17];
    const float* sgw    = (const float*)d_in[18];
    const float* suw    = (const float*)d_in[19];
    const float* sdw    = (const float*)d_in[20];
    const float* shgw   = (const float*)d_in[21];
    float* out = (float*)d_out;

    float* buf;  cudaGetSymbolAddress((void**)&buf,  g_buf);
    int*   cnt;  cudaGetSymbolAddress((void**)&cnt,  g_cnt);
    int*   tokA; cudaGetSymbolAddress((void**)&tokA, g_tokA);
    int*   dstC; cudaGetSymbolAddress((void**)&dstC, g_dstC);

    // 1. rmsnorm 1
    rmsnorm_kernel<<<Tt, 256>>>(x, ln1, buf + O_H1);

    // 2. QKV projections (+bias)
    gemm(false, buf + O_H1, Dd, qw, HD, buf + O_Q, HD, Tt, HD, Dd, qb, nullptr, nullptr, nullptr);
    gemm(false, buf + O_H1, Dd, kw, HD, buf + O_K, HD, Tt, HD, Dd, kb, nullptr, nullptr, nullptr);
    gemm(false, buf + O_H1, Dd, vw, HD, buf + O_V, HD, Tt, HD, Dd, vb, nullptr, nullptr, nullptr);

    // 3. RoPE on q, k
    rope_kernel<<<Tt * Hh, DHh>>>(buf + O_Q, buf + O_K, pos, sin_t, cos_t);

    // 4. scores = Q @ K^T  (batched over B*H)
    gemm(true, buf + O_Q, HD, buf + O_K, HD, buf + O_SC, Ss,
         Ss, Ss, DHh, nullptr, nullptr, nullptr, nullptr,
         Bb * Hh, Hh,
         /*aI*/ DHh, /*aO*/ (long)Ss * HD,
         /*bI*/ DHh, /*bO*/ (long)Ss * HD,
         /*cI*/ (long)Ss * Ss, /*cO*/ (long)Hh * Ss * Ss);

    // 5. masked causal softmax (in place)
    softmax_kernel<<<Bb * Hh * Ss, 256>>>(buf + O_SC, amask);

    // 6. attn = P @ V
    gemm(false, buf + O_SC, Ss, buf + O_V, HD, buf + O_ATT, HD,
         Ss, DHh, Ss, nullptr, nullptr, nullptr, nullptr,
         Bb * Hh, Hh,
         /*aI*/ (long)Ss * Ss, /*aO*/ (long)Hh * Ss * Ss,
         /*bI*/ DHh, /*bO*/ (long)Ss * HD,
         /*cI*/ DHh, /*cO*/ (long)Ss * HD);

    // 7. O projection (reuse O_H1 as scratch)
    gemm(false, buf + O_ATT, HD, ow, Dd, buf + O_H1, Dd, Tt, Dd, HD,
         nullptr, nullptr, nullptr, nullptr);

    // 8. residual: h = x + attn_out
    add_kernel<<<(int)(TD / 4 / 256), 256>>>((const float4*)x,
                                             (const float4*)(buf + O_H1),
                                             (float4*)(buf + O_RES));

    // 9. rmsnorm 2
    rmsnorm_kernel<<<Tt, 256>>>(buf + O_RES, ln2, buf + O_H2);

    // 10. routing (+ shared gate)
    zero_cnt_kernel<<<1, 32>>>(cnt);
    router_kernel<<<Tt, 256>>>(buf + O_H2, rtw, shgw,
                               buf + O_TOPV, buf + O_SGATE, cnt, tokA, dstC);

    // 11. expert gate/up GEMMs (gathered tokens, scattered to (t,k) rows)
    for (int e = 0; e < Ee; ++e) {
        gemm(false, buf + O_H2, Dd, egw + (long)e * Dd * Ii, Ii,
             buf + O_G, Ii, Tt, Ii, Dd,
             nullptr, cnt + e, tokA + e * Tt, dstC + e * Tt);
        gemm(false, buf + O_H2, Dd, euw + (long)e * Dd * Ii, Ii,
             buf + O_U, Ii, Tt, Ii, Dd,
             nullptr, cnt + e, tokA + e * Tt, dstC + e * Tt);
    }

    // 12. act = silu(g) * u * topv
    act_moe_kernel<<<(int)((GSZ / 4 + 255) / 256), 256>>>(
        (float4*)(buf + O_G), (const float4*)(buf + O_U), buf + O_TOPV);

    // 13. expert down GEMMs -> per-(t,k) slot
    for (int e = 0; e < Ee; ++e) {
        gemm(false, buf + O_G, Ii, edw + (long)e * Ii * Dd, Dd,
             buf + O_MOE, Dd, Tt, Dd, Ii,
             nullptr, cnt + e, dstC + e * Tt, dstC + e * Tt);
    }

    // 14. shared expert
    gemm(false, buf + O_H2, Dd, sgw, ISs, buf + O_SG, ISs, Tt, ISs, Dd,
         nullptr, nullptr, nullptr, nullptr);
    gemm(false, buf + O_H2, Dd, suw, ISs, buf + O_SU, ISs, Tt, ISs, Dd,
         nullptr, nullptr, nullptr, nullptr);
    act_shared_kernel<<<(int)((SGSZ / 4 + 255) / 256), 256>>>(
        (float4*)(buf + O_SG), (const float4*)(buf + O_SU));
    gemm(false, buf + O_SG, ISs, sdw, Dd, buf + O_SH, Dd, Tt, Dd, ISs,
         nullptr, nullptr, nullptr, nullptr);

    // 15. final combine
    combine_kernel<<<(int)(TD / 4 / 256), 256>>>(
        (const float4*)(buf + O_RES), (const float4*)(buf + O_MOE),
        (const float4*)(buf + O_SH), buf + O_SGATE, (float4*)out);
}